// round 3
// baseline (speedup 1.0000x reference)
#include <cuda_runtime.h>
#include <math.h>

// Problem constants
#define BATCH 16
#define SEQ   1024
#define DIM   1024
#define MTOT  (BATCH*SEQ)            // 16384
#define MS    ((size_t)MTOT*DIM)     // 16777216 elems per projection buffer
#define SD    ((size_t)SEQ*DIM)      // per-batch stride (== SEQ*SEQ here)

// Scratch (device globals: allowed; cudaMalloc is not)
__device__ float g_proj[6 * MS];                       // qr,qi,kr,ki,vr,vi
__device__ float g_scores[(size_t)BATCH * SEQ * SEQ];  // scores/attn in place

// ---------------------------------------------------------------------------
// Tiled fp32 GEMM: C[M,N] = alpha * A @ opB + (BIAS? bias : 0) + (ACCUM? C : 0)
// BMODE==0: B is [N,K] row-major (contract over its columns, i.e. A @ B^T)
// BMODE==1: B is [K,N] row-major (plain A @ B)
// All of M,N multiples of 128; K multiple of 8. Block tile 128x128x8,
// 256 threads, 8x8 per-thread microtile, float4 everywhere.
// ---------------------------------------------------------------------------
template<int BMODE, bool BIAS, bool ACCUM>
__global__ __launch_bounds__(256)
void gemm128(const float* __restrict__ A, const float* __restrict__ Bm,
             const float* __restrict__ bias, float* __restrict__ C,
             int K, int lda, int ldb, int ldc,
             size_t sA, size_t sB, size_t sC, float alpha)
{
    __shared__ float As[8][128];
    __shared__ float Bs[8][128];

    const int bx = blockIdx.x;           // N tile
    const int by = blockIdx.y;           // M tile
    const size_t bz = blockIdx.z;        // batch

    A += bz * sA + (size_t)by * 128 * lda;
    C += bz * sC + (size_t)by * 128 * ldc + (size_t)bx * 128;
    if (BMODE == 0) Bm += bz * sB + (size_t)bx * 128 * ldb;
    else            Bm += bz * sB + (size_t)bx * 128;
    if (BIAS) bias += (size_t)bx * 128;

    const int tid = threadIdx.x;
    const int aRow = tid >> 1;
    const int aCol = (tid & 1) * 4;
    int bRow, bCol;
    if (BMODE == 0) { bRow = tid >> 1; bCol = (tid & 1) * 4; }
    else            { bRow = tid >> 5; bCol = (tid & 31) * 4; }

    const int tx = tid & 15;
    const int ty = tid >> 4;

    float acc[8][8];
    #pragma unroll
    for (int i = 0; i < 8; i++)
        #pragma unroll
        for (int j = 0; j < 8; j++) acc[i][j] = 0.f;

    for (int k0 = 0; k0 < K; k0 += 8) {
        float4 av = *(const float4*)(A + (size_t)aRow * lda + k0 + aCol);
        As[aCol + 0][aRow] = av.x;
        As[aCol + 1][aRow] = av.y;
        As[aCol + 2][aRow] = av.z;
        As[aCol + 3][aRow] = av.w;

        if (BMODE == 0) {
            float4 bv = *(const float4*)(Bm + (size_t)bRow * ldb + k0 + bCol);
            Bs[bCol + 0][bRow] = bv.x;
            Bs[bCol + 1][bRow] = bv.y;
            Bs[bCol + 2][bRow] = bv.z;
            Bs[bCol + 3][bRow] = bv.w;
        } else {
            float4 bv = *(const float4*)(Bm + (size_t)(k0 + bRow) * ldb + bCol);
            *(float4*)&Bs[bRow][bCol] = bv;
        }
        __syncthreads();

        #pragma unroll
        for (int kk = 0; kk < 8; kk++) {
            float a[8], b[8];
            *(float4*)&a[0] = *(const float4*)&As[kk][ty * 8];
            *(float4*)&a[4] = *(const float4*)&As[kk][ty * 8 + 4];
            *(float4*)&b[0] = *(const float4*)&Bs[kk][tx * 8];
            *(float4*)&b[4] = *(const float4*)&Bs[kk][tx * 8 + 4];
            #pragma unroll
            for (int i = 0; i < 8; i++)
                #pragma unroll
                for (int j = 0; j < 8; j++)
                    acc[i][j] = fmaf(a[i], b[j], acc[i][j]);
        }
        __syncthreads();
    }

    #pragma unroll
    for (int i = 0; i < 8; i++) {
        const int row = ty * 8 + i;
        #pragma unroll
        for (int j = 0; j < 8; j += 4) {
            const int col = tx * 8 + j;
            float4 r;
            r.x = acc[i][j + 0] * alpha;
            r.y = acc[i][j + 1] * alpha;
            r.z = acc[i][j + 2] * alpha;
            r.w = acc[i][j + 3] * alpha;
            if (BIAS) {
                r.x += bias[col + 0]; r.y += bias[col + 1];
                r.z += bias[col + 2]; r.w += bias[col + 3];
            }
            float4* cp = (float4*)(C + (size_t)row * ldc + col);
            if (ACCUM) {
                float4 c0 = *cp;
                r.x += c0.x; r.y += c0.y; r.z += c0.z; r.w += c0.w;
            }
            *cp = r;
        }
    }
}

// ---------------------------------------------------------------------------
// Row softmax, in place. One block (256 threads) per row of 1024.
// ---------------------------------------------------------------------------
__global__ __launch_bounds__(256)
void softmax_kernel(float* __restrict__ s)
{
    const size_t row = blockIdx.x;
    float4* p = (float4*)(s + row * 1024);
    const int tid = threadIdx.x;

    float4 v = p[tid];
    float m = fmaxf(fmaxf(v.x, v.y), fmaxf(v.z, v.w));
    #pragma unroll
    for (int o = 16; o > 0; o >>= 1)
        m = fmaxf(m, __shfl_xor_sync(0xffffffffu, m, o));

    __shared__ float red[8];
    __shared__ float fin[2];
    if ((tid & 31) == 0) red[tid >> 5] = m;
    __syncthreads();
    if (tid < 32) {
        float t = (tid < 8) ? red[tid] : -3.4e38f;
        #pragma unroll
        for (int o = 4; o > 0; o >>= 1)
            t = fmaxf(t, __shfl_xor_sync(0xffffffffu, t, o));
        if (tid == 0) fin[0] = t;
    }
    __syncthreads();
    m = fin[0];

    v.x = expf(v.x - m); v.y = expf(v.y - m);
    v.z = expf(v.z - m); v.w = expf(v.w - m);
    float sum = v.x + v.y + v.z + v.w;
    #pragma unroll
    for (int o = 16; o > 0; o >>= 1)
        sum += __shfl_xor_sync(0xffffffffu, sum, o);
    if ((tid & 31) == 0) red[tid >> 5] = sum;
    __syncthreads();
    if (tid < 32) {
        float t = (tid < 8) ? red[tid] : 0.f;
        #pragma unroll
        for (int o = 4; o > 0; o >>= 1)
            t += __shfl_xor_sync(0xffffffffu, t, o);
        if (tid == 0) fin[1] = t;
    }
    __syncthreads();
    const float inv = 1.0f / fin[1];
    v.x *= inv; v.y *= inv; v.z *= inv; v.w *= inv;
    p[tid] = v;
}

// ---------------------------------------------------------------------------
// Complex LayerNorm, in place on out = [2, B*S, D] (real plane then imag).
// mean/var in COMPLEX arithmetic; std = principal complex sqrt(var + eps);
// y = a2 * (z - mean)/std + b2  (b2 adds to real part only).
// One block (256 threads) per row.
// ---------------------------------------------------------------------------
__global__ __launch_bounds__(256)
void complex_ln_kernel(float* __restrict__ out,
                       const float* __restrict__ a2,
                       const float* __restrict__ b2)
{
    const size_t row = blockIdx.x;
    float* pr = out + row * 1024;
    float* pi = out + MS + row * 1024;
    const int tid = threadIdx.x;

    float4 zr = ((float4*)pr)[tid];
    float4 zi = ((float4*)pi)[tid];

    float sv[5];
    sv[0] = zr.x + zr.y + zr.z + zr.w;                               // sum r
    sv[1] = zi.x + zi.y + zi.z + zi.w;                               // sum i
    sv[2] = zr.x*zr.x + zr.y*zr.y + zr.z*zr.z + zr.w*zr.w;           // sum r^2
    sv[3] = zi.x*zi.x + zi.y*zi.y + zi.z*zi.z + zi.w*zi.w;           // sum i^2
    sv[4] = zr.x*zi.x + zr.y*zi.y + zr.z*zi.z + zr.w*zi.w;           // sum r*i

    #pragma unroll
    for (int u = 0; u < 5; u++)
        #pragma unroll
        for (int o = 16; o > 0; o >>= 1)
            sv[u] += __shfl_xor_sync(0xffffffffu, sv[u], o);

    __shared__ float red[5][8];
    __shared__ float fin[5];
    if ((tid & 31) == 0) {
        #pragma unroll
        for (int u = 0; u < 5; u++) red[u][tid >> 5] = sv[u];
    }
    __syncthreads();
    if (tid == 0) {
        #pragma unroll
        for (int u = 0; u < 5; u++) {
            float t = 0.f;
            #pragma unroll
            for (int w = 0; w < 8; w++) t += red[u][w];
            fin[u] = t;
        }
    }
    __syncthreads();

    const float invD = 1.0f / 1024.0f;
    const float mr = fin[0] * invD;
    const float mi = fin[1] * invD;
    const float err = fin[2] * invD - mr * mr;   // E[zr'^2]
    const float eii = fin[3] * invD - mi * mi;   // E[zi'^2]
    const float eri = fin[4] * invD - mr * mi;   // E[zr'zi']
    const float vr = err - eii + 1e-6f;          // complex var real + eps
    const float vi = 2.0f * eri;                 // complex var imag
    const float rmod = sqrtf(vr * vr + vi * vi);
    const float sre = sqrtf(fmaxf(0.5f * (rmod + vr), 0.f));
    const float sim = copysignf(sqrtf(fmaxf(0.5f * (rmod - vr), 0.f)), vi);
    const float inv = 1.0f / fmaxf(rmod, 1e-30f);   // sre^2 + sim^2 == rmod

    float4 ga = ((const float4*)a2)[tid];
    float4 gb = ((const float4*)b2)[tid];

    float4 yr, yi;
    {
        float ar = zr.x - mr, ai = zi.x - mi;
        yr.x = (ar * sre + ai * sim) * inv; yi.x = (ai * sre - ar * sim) * inv;
        ar = zr.y - mr; ai = zi.y - mi;
        yr.y = (ar * sre + ai * sim) * inv; yi.y = (ai * sre - ar * sim) * inv;
        ar = zr.z - mr; ai = zi.z - mi;
        yr.z = (ar * sre + ai * sim) * inv; yi.z = (ai * sre - ar * sim) * inv;
        ar = zr.w - mr; ai = zi.w - mi;
        yr.w = (ar * sre + ai * sim) * inv; yi.w = (ai * sre - ar * sim) * inv;
    }
    yr.x = ga.x * yr.x + gb.x; yi.x = ga.x * yi.x;
    yr.y = ga.y * yr.y + gb.y; yi.y = ga.y * yi.y;
    yr.z = ga.z * yr.z + gb.z; yi.z = ga.z * yi.z;
    yr.w = ga.w * yr.w + gb.w; yi.w = ga.w * yi.w;

    ((float4*)pr)[tid] = yr;
    ((float4*)pi)[tid] = yi;
}

// ---------------------------------------------------------------------------
extern "C" void kernel_launch(void* const* d_in, const int* in_sizes, int n_in,
                              void* d_out, int out_size)
{
    // metadata order: q_real q_imag k_real k_imag v_real v_imag,
    // Wq_r bq_r Wq_i bq_i Wk_r bk_r Wk_i bk_i Wv_r bv_r Wv_i bv_i, a_2 b_2
    const float* X[6]  = { (const float*)d_in[0], (const float*)d_in[1],
                           (const float*)d_in[2], (const float*)d_in[3],
                           (const float*)d_in[4], (const float*)d_in[5] };
    const float* W[6]  = { (const float*)d_in[6],  (const float*)d_in[8],
                           (const float*)d_in[10], (const float*)d_in[12],
                           (const float*)d_in[14], (const float*)d_in[16] };
    const float* Bv[6] = { (const float*)d_in[7],  (const float*)d_in[9],
                           (const float*)d_in[11], (const float*)d_in[13],
                           (const float*)d_in[15], (const float*)d_in[17] };
    const float* a2 = (const float*)d_in[18];
    const float* b2 = (const float*)d_in[19];
    float* out = (float*)d_out;

    float *proj = nullptr, *scores = nullptr;
    cudaGetSymbolAddress((void**)&proj, g_proj);
    cudaGetSymbolAddress((void**)&scores, g_scores);

    float* qr = proj + 0 * MS;
    float* qi = proj + 1 * MS;
    float* kr = proj + 2 * MS;
    float* ki = proj + 3 * MS;
    float* vr = proj + 4 * MS;
    float* vi = proj + 5 * MS;
    float* P[6] = { qr, qi, kr, ki, vr, vi };

    // 1) Six projections: P = X @ W^T + b   (W is [N,K] row-major -> BMODE 0)
    {
        dim3 grid(DIM / 128, MTOT / 128, 1);
        for (int j = 0; j < 6; j++)
            gemm128<0, true, false><<<grid, 256>>>(
                X[j], W[j], Bv[j], P[j],
                DIM, DIM, DIM, DIM, 0, 0, 0, 1.0f);
    }

    // 2) scores = (qr @ kr + qi @ ki^T) / 8, batched over 16
    {
        dim3 grid(SEQ / 128, SEQ / 128, BATCH);
        gemm128<1, false, false><<<grid, 256>>>(
            qr, kr, nullptr, scores,
            DIM, DIM, DIM, SEQ, SD, SD, SD, 0.125f);
        gemm128<0, false, true><<<grid, 256>>>(
            qi, ki, nullptr, scores,
            DIM, DIM, DIM, SEQ, SD, SD, SD, 0.125f);
    }

    // 3) softmax over last dim, in place
    softmax_kernel<<<MTOT, 256>>>(scores);

    // 4) out_r = attn @ vr -> out[0], out_i = attn @ vi -> out[1]
    {
        dim3 grid(DIM / 128, SEQ / 128, BATCH);
        gemm128<1, false, false><<<grid, 256>>>(
            scores, vr, nullptr, out,
            SEQ, SEQ, DIM, DIM, SD, SD, SD, 1.0f);
        gemm128<1, false, false><<<grid, 256>>>(
            scores, vi, nullptr, out + MS,
            SEQ, SEQ, DIM, DIM, SD, SD, SD, 1.0f);
    }

    // 5) complex LayerNorm in place on d_out
    complex_ln_kernel<<<MTOT, 256>>>(out, a2, b2);
}

// round 6
// speedup vs baseline: 2.1919x; 2.1919x over previous
#include <cuda_runtime.h>
#include <cuda_bf16.h>
#include <math.h>
#include <stdint.h>

// Problem constants
#define BATCH 16
#define SEQ   1024
#define DIM   1024
#define MTOT  (BATCH*SEQ)            // 16384
#define MS    ((size_t)MTOT*DIM)     // 16777216
#define SD    ((size_t)SEQ*DIM)      // per-batch stride
#define WS    ((size_t)DIM*DIM)

// bf16 hi/lo planes (device globals; cudaMalloc forbidden)
__device__ __nv_bfloat16 g_xhi[6*MS], g_xlo[6*MS];
__device__ __nv_bfloat16 g_whi[6*WS], g_wlo[6*WS];
// proj planes, slots: 0 qr, 1 qi, 2 krT, 3 ki, 4 vrT, 5 viT
__device__ __nv_bfloat16 g_phi[6*MS], g_plo[6*MS];
__device__ __nv_bfloat16 g_ahi[MS],  g_alo[MS];
__device__ float g_scores[(size_t)BATCH*SEQ*SEQ];

// ---------------------------------------------------------------------------
// helpers
// ---------------------------------------------------------------------------
__device__ __forceinline__ uint32_t smem_u32(const void* p) {
    uint32_t r;
    asm("{ .reg .u64 t; cvta.to.shared.u64 t, %1; cvt.u32.u64 %0, t; }"
        : "=r"(r) : "l"(p));
    return r;
}

__device__ __forceinline__ void cp16(uint32_t d, const void* s) {
    asm volatile("cp.async.cg.shared.global [%0], [%1], 16;" :: "r"(d), "l"(s));
}

__device__ __forceinline__ void ldmx4(uint32_t& r0, uint32_t& r1,
                                      uint32_t& r2, uint32_t& r3, uint32_t a) {
    asm volatile("ldmatrix.sync.aligned.m8n8.x4.shared.b16 {%0,%1,%2,%3}, [%4];"
                 : "=r"(r0), "=r"(r1), "=r"(r2), "=r"(r3) : "r"(a));
}

__device__ __forceinline__ void mma16816(float* c, const uint32_t* a,
                                         const uint32_t* b) {
    asm volatile(
        "mma.sync.aligned.m16n8k16.row.col.f32.bf16.bf16.f32 "
        "{%0,%1,%2,%3}, {%4,%5,%6,%7}, {%8,%9}, {%0,%1,%2,%3};"
        : "+f"(c[0]), "+f"(c[1]), "+f"(c[2]), "+f"(c[3])
        : "r"(a[0]), "r"(a[1]), "r"(a[2]), "r"(a[3]), "r"(b[0]), "r"(b[1]));
}

__device__ __forceinline__ void fsplit(float x, __nv_bfloat16& h, float& l) {
    h = __float2bfloat16(x);
    l = x - __bfloat162float(h);
}

// ---------------------------------------------------------------------------
// fp32 -> (hi, lo) bf16 planes, elementwise
// ---------------------------------------------------------------------------
__global__ __launch_bounds__(256)
void conv_split(const float4* __restrict__ in, __nv_bfloat162* __restrict__ hi,
                __nv_bfloat162* __restrict__ lo, size_t n4)
{
    size_t i = (size_t)blockIdx.x * 256 + threadIdx.x;
    if (i >= n4) return;
    float4 v = in[i];
    __nv_bfloat16 h0, h1, h2, h3; float l0, l1, l2, l3;
    fsplit(v.x, h0, l0); fsplit(v.y, h1, l1);
    fsplit(v.z, h2, l2); fsplit(v.w, h3, l3);
    hi[2*i]   = __halves2bfloat162(h0, h1);
    hi[2*i+1] = __halves2bfloat162(h2, h3);
    lo[2*i]   = __halves2bfloat162(__float2bfloat16(l0), __float2bfloat16(l1));
    lo[2*i+1] = __halves2bfloat162(__float2bfloat16(l2), __float2bfloat16(l3));
}

// ---------------------------------------------------------------------------
// Split-bf16 HMMA GEMM.
// C[m,n] = sum_seg  Aseg[m,:] . Bseg[n,:]   (all operands row-major, ld=1024,
// contraction over the 1024-long rows; segments implement the hi/lo products)
// Tile 128x128, BK=32, 8 warps (4x2), warp tile 32x64, mma m16n8k16.
// Epilogues: 0 = fp32*alpha, 1 = +bias -> split planes, 2 = +bias -> split
// planes with per-batch transpose (plane[b][col][row%1024]).
// ---------------------------------------------------------------------------
#define RS 40                     // smem row stride in bf16 (80B, conflict-free)
#define OPBYTES (128*RS*2)        // 10240 per operand per stage

struct SegPtrs { const __nv_bfloat16* a[6]; const __nv_bfloat16* b[6]; };

template<int EPI>
__global__ __launch_bounds__(256)
void tc_gemm(SegPtrs segs, int nseg, size_t sA, size_t sB,
             float* __restrict__ Cf, size_t sC, float alpha,
             const float* __restrict__ bias,
             __nv_bfloat16* __restrict__ hiP, __nv_bfloat16* __restrict__ loP)
{
    __shared__ __align__(128) char sm[2 * 2 * OPBYTES];   // 2 stages x (A,B)
    __shared__ const __nv_bfloat16* sAp[6];
    __shared__ const __nv_bfloat16* sBp[6];

    const int tid = threadIdx.x;
    const int m0 = blockIdx.y * 128;
    const int n0 = blockIdx.x * 128;
    const size_t bz = blockIdx.z;

    if (tid < 6 && tid < nseg) {
        sAp[tid] = segs.a[tid] + bz * sA + (size_t)m0 * 1024;
        sBp[tid] = segs.b[tid] + bz * sB + (size_t)n0 * 1024;
    }
    __syncthreads();

    const uint32_t smb = smem_u32(sm);
    const int r0 = tid >> 2, c0 = tid & 3;
    const int NIT = nseg * 32;

    auto issue = [&](int it) {
        const int seg = it >> 5, kc = it & 31;
        const uint32_t st = smb + (uint32_t)(it & 1) * (2 * OPBYTES);
        const __nv_bfloat16* ga = sAp[seg] + kc * 32;
        const __nv_bfloat16* gb = sBp[seg] + kc * 32;
        cp16(st + r0 * 80 + c0 * 16,            ga + (size_t)r0 * 1024 + c0 * 8);
        cp16(st + (r0 + 64) * 80 + c0 * 16,     ga + (size_t)(r0 + 64) * 1024 + c0 * 8);
        cp16(st + OPBYTES + r0 * 80 + c0 * 16,        gb + (size_t)r0 * 1024 + c0 * 8);
        cp16(st + OPBYTES + (r0 + 64) * 80 + c0 * 16, gb + (size_t)(r0 + 64) * 1024 + c0 * 8);
    };

    float acc[2][8][4];
    #pragma unroll
    for (int i = 0; i < 2; i++)
        #pragma unroll
        for (int j = 0; j < 8; j++)
            #pragma unroll
            for (int k = 0; k < 4; k++) acc[i][j][k] = 0.f;

    const int lane = tid & 31, w = tid >> 5;
    const int wm = (w >> 1) * 32;      // warp M offset (0,32,64,96)
    const int wn = (w & 1) * 64;       // warp N offset (0,64)
    const uint32_t lmo = (uint32_t)((lane & 15) * 80 + (lane >> 4) * 16);

    issue(0);
    asm volatile("cp.async.commit_group;" ::: "memory");

    for (int it = 0; it < NIT; ++it) {
        if (it + 1 < NIT) issue(it + 1);
        asm volatile("cp.async.commit_group;" ::: "memory");
        asm volatile("cp.async.wait_group 1;" ::: "memory");
        __syncthreads();

        const uint32_t stg = smb + (uint32_t)(it & 1) * (2 * OPBYTES);
        const uint32_t sa = stg + wm * 80 + lmo;
        const uint32_t sb = stg + OPBYTES + wn * 80 + lmo;

        #pragma unroll
        for (int ks = 0; ks < 2; ks++) {
            uint32_t A0[4], A1[4], Bf[8][2];
            ldmx4(A0[0], A0[1], A0[2], A0[3], sa + ks * 32);
            ldmx4(A1[0], A1[1], A1[2], A1[3], sa + 1280 + ks * 32);
            #pragma unroll
            for (int q = 0; q < 4; q++) {
                uint32_t t0, t1, t2, t3;
                ldmx4(t0, t1, t2, t3, sb + q * 1280 + ks * 32);
                Bf[2*q][0] = t0; Bf[2*q][1] = t2;
                Bf[2*q+1][0] = t1; Bf[2*q+1][1] = t3;
            }
            #pragma unroll
            for (int nt = 0; nt < 8; nt++) {
                mma16816(acc[0][nt], A0, Bf[nt]);
                mma16816(acc[1][nt], A1, Bf[nt]);
            }
        }
        __syncthreads();
    }

    // Epilogue. C frag: lane g=lane>>2,t=lane&3: c0,c1 -> (row g, col 2t,2t+1),
    // c2,c3 -> (row g+8, same cols).
    const int g = lane >> 2, t4 = lane & 3;
    #pragma unroll
    for (int mt = 0; mt < 2; mt++) {
        #pragma unroll
        for (int nt = 0; nt < 8; nt++) {
            const int rowA = m0 + wm + mt * 16 + g;
            const int rowB = rowA + 8;
            const int col  = n0 + wn + nt * 8 + 2 * t4;
            float c0 = acc[mt][nt][0], c1 = acc[mt][nt][1];
            float c2 = acc[mt][nt][2], c3 = acc[mt][nt][3];
            if (EPI == 0) {
                float2 v0 = make_float2(c0 * alpha, c1 * alpha);
                float2 v1 = make_float2(c2 * alpha, c3 * alpha);
                *(float2*)(Cf + bz * sC + (size_t)rowA * 1024 + col) = v0;
                *(float2*)(Cf + bz * sC + (size_t)rowB * 1024 + col) = v1;
            } else {
                const float b0v = bias[col], b1v = bias[col + 1];
                const float v0 = c0 + b0v, v1 = c1 + b1v;
                const float v2 = c2 + b0v, v3 = c3 + b1v;
                __nv_bfloat16 h0, h1, h2, h3; float l0, l1, l2, l3;
                fsplit(v0, h0, l0); fsplit(v1, h1, l1);
                fsplit(v2, h2, l2); fsplit(v3, h3, l3);
                if (EPI == 1) {
                    *(__nv_bfloat162*)(hiP + (size_t)rowA * 1024 + col) =
                        __halves2bfloat162(h0, h1);
                    *(__nv_bfloat162*)(hiP + (size_t)rowB * 1024 + col) =
                        __halves2bfloat162(h2, h3);
                    *(__nv_bfloat162*)(loP + (size_t)rowA * 1024 + col) =
                        __halves2bfloat162(__float2bfloat16(l0), __float2bfloat16(l1));
                    *(__nv_bfloat162*)(loP + (size_t)rowB * 1024 + col) =
                        __halves2bfloat162(__float2bfloat16(l2), __float2bfloat16(l3));
                } else {   // EPI==2: per-batch transposed planes [b][col][s]
                    const size_t bb = (size_t)(rowA >> 10) * (1024 * 1024);
                    const int sA_ = rowA & 1023, sB_ = rowB & 1023;
                    hiP[bb + (size_t)col * 1024 + sA_]       = h0;
                    hiP[bb + (size_t)(col + 1) * 1024 + sA_] = h1;
                    hiP[bb + (size_t)col * 1024 + sB_]       = h2;
                    hiP[bb + (size_t)(col + 1) * 1024 + sB_] = h3;
                    loP[bb + (size_t)col * 1024 + sA_]       = __float2bfloat16(l0);
                    loP[bb + (size_t)(col + 1) * 1024 + sA_] = __float2bfloat16(l1);
                    loP[bb + (size_t)col * 1024 + sB_]       = __float2bfloat16(l2);
                    loP[bb + (size_t)(col + 1) * 1024 + sB_] = __float2bfloat16(l3);
                }
            }
        }
    }
}

// ---------------------------------------------------------------------------
// Row softmax over 1024, writes attn hi/lo bf16 planes.
// ---------------------------------------------------------------------------
__global__ __launch_bounds__(256)
void softmax_split(const float* __restrict__ s, __nv_bfloat16* __restrict__ hi,
                   __nv_bfloat16* __restrict__ lo)
{
    const size_t row = blockIdx.x;
    const float4* p = (const float4*)(s + row * 1024);
    const int tid = threadIdx.x;

    float4 v = p[tid];
    float m = fmaxf(fmaxf(v.x, v.y), fmaxf(v.z, v.w));
    #pragma unroll
    for (int o = 16; o > 0; o >>= 1)
        m = fmaxf(m, __shfl_xor_sync(0xffffffffu, m, o));

    __shared__ float red[8];
    __shared__ float fin[2];
    if ((tid & 31) == 0) red[tid >> 5] = m;
    __syncthreads();
    if (tid < 32) {
        float t = (tid < 8) ? red[tid] : -3.4e38f;
        #pragma unroll
        for (int o = 4; o > 0; o >>= 1)
            t = fmaxf(t, __shfl_xor_sync(0xffffffffu, t, o));
        if (tid == 0) fin[0] = t;
    }
    __syncthreads();
    m = fin[0];

    v.x = expf(v.x - m); v.y = expf(v.y - m);
    v.z = expf(v.z - m); v.w = expf(v.w - m);
    float sum = v.x + v.y + v.z + v.w;
    #pragma unroll
    for (int o = 16; o > 0; o >>= 1)
        sum += __shfl_xor_sync(0xffffffffu, sum, o);
    if ((tid & 31) == 0) red[tid >> 5] = sum;
    __syncthreads();
    if (tid < 32) {
        float t = (tid < 8) ? red[tid] : 0.f;
        #pragma unroll
        for (int o = 4; o > 0; o >>= 1)
            t += __shfl_xor_sync(0xffffffffu, t, o);
        if (tid == 0) fin[1] = t;
    }
    __syncthreads();
    const float inv = 1.0f / fin[1];
    v.x *= inv; v.y *= inv; v.z *= inv; v.w *= inv;

    __nv_bfloat16 h0, h1, h2, h3; float l0, l1, l2, l3;
    fsplit(v.x, h0, l0); fsplit(v.y, h1, l1);
    fsplit(v.z, h2, l2); fsplit(v.w, h3, l3);
    __nv_bfloat162* ph = (__nv_bfloat162*)(hi + row * 1024 + tid * 4);
    __nv_bfloat162* pl = (__nv_bfloat162*)(lo + row * 1024 + tid * 4);
    ph[0] = __halves2bfloat162(h0, h1);
    ph[1] = __halves2bfloat162(h2, h3);
    pl[0] = __halves2bfloat162(__float2bfloat16(l0), __float2bfloat16(l1));
    pl[1] = __halves2bfloat162(__float2bfloat16(l2), __float2bfloat16(l3));
}

// ---------------------------------------------------------------------------
// Complex LayerNorm, in place on out = [2, B*S, D].
// ---------------------------------------------------------------------------
__global__ __launch_bounds__(256)
void complex_ln_kernel(float* __restrict__ out,
                       const float* __restrict__ a2,
                       const float* __restrict__ b2)
{
    const size_t row = blockIdx.x;
    float* pr = out + row * 1024;
    float* pi = out + MS + row * 1024;
    const int tid = threadIdx.x;

    float4 zr = ((float4*)pr)[tid];
    float4 zi = ((float4*)pi)[tid];

    float sv[5];
    sv[0] = zr.x + zr.y + zr.z + zr.w;
    sv[1] = zi.x + zi.y + zi.z + zi.w;
    sv[2] = zr.x*zr.x + zr.y*zr.y + zr.z*zr.z + zr.w*zr.w;
    sv[3] = zi.x*zi.x + zi.y*zi.y + zi.z*zi.z + zi.w*zi.w;
    sv[4] = zr.x*zi.x + zr.y*zi.y + zr.z*zi.z + zr.w*zi.w;

    #pragma unroll
    for (int u = 0; u < 5; u++)
        #pragma unroll
        for (int o = 16; o > 0; o >>= 1)
            sv[u] += __shfl_xor_sync(0xffffffffu, sv[u], o);

    __shared__ float red[5][8];
    __shared__ float fin[5];
    if ((tid & 31) == 0) {
        #pragma unroll
        for (int u = 0; u < 5; u++) red[u][tid >> 5] = sv[u];
    }
    __syncthreads();
    if (tid == 0) {
        #pragma unroll
        for (int u = 0; u < 5; u++) {
            float t = 0.f;
            #pragma unroll
            for (int wv = 0; wv < 8; wv++) t += red[u][wv];
            fin[u] = t;
        }
    }
    __syncthreads();

    const float invD = 1.0f / 1024.0f;
    const float mr = fin[0] * invD;
    const float mi = fin[1] * invD;
    const float err = fin[2] * invD - mr * mr;
    const float eii = fin[3] * invD - mi * mi;
    const float eri = fin[4] * invD - mr * mi;
    const float vr = err - eii + 1e-6f;
    const float vi = 2.0f * eri;
    const float rmod = sqrtf(vr * vr + vi * vi);
    const float sre = sqrtf(fmaxf(0.5f * (rmod + vr), 0.f));
    const float sim = copysignf(sqrtf(fmaxf(0.5f * (rmod - vr), 0.f)), vi);
    const float inv = 1.0f / fmaxf(rmod, 1e-30f);

    float4 ga = ((const float4*)a2)[tid];
    float4 gb = ((const float4*)b2)[tid];

    float4 yr, yi;
    {
        float ar = zr.x - mr, ai = zi.x - mi;
        yr.x = (ar * sre + ai * sim) * inv; yi.x = (ai * sre - ar * sim) * inv;
        ar = zr.y - mr; ai = zi.y - mi;
        yr.y = (ar * sre + ai * sim) * inv; yi.y = (ai * sre - ar * sim) * inv;
        ar = zr.z - mr; ai = zi.z - mi;
        yr.z = (ar * sre + ai * sim) * inv; yi.z = (ai * sre - ar * sim) * inv;
        ar = zr.w - mr; ai = zi.w - mi;
        yr.w = (ar * sre + ai * sim) * inv; yi.w = (ai * sre - ar * sim) * inv;
    }
    yr.x = ga.x * yr.x + gb.x; yi.x = ga.x * yi.x;
    yr.y = ga.y * yr.y + gb.y; yi.y = ga.y * yi.y;
    yr.z = ga.z * yr.z + gb.z; yi.z = ga.z * yi.z;
    yr.w = ga.w * yr.w + gb.w; yi.w = ga.w * yi.w;

    ((float4*)pr)[tid] = yr;
    ((float4*)pi)[tid] = yi;
}

// ---------------------------------------------------------------------------
extern "C" void kernel_launch(void* const* d_in, const int* in_sizes, int n_in,
                              void* d_out, int out_size)
{
    const float* X[6]  = { (const float*)d_in[0], (const float*)d_in[1],
                           (const float*)d_in[2], (const float*)d_in[3],
                           (const float*)d_in[4], (const float*)d_in[5] };
    const float* W[6]  = { (const float*)d_in[6],  (const float*)d_in[8],
                           (const float*)d_in[10], (const float*)d_in[12],
                           (const float*)d_in[14], (const float*)d_in[16] };
    const float* Bv[6] = { (const float*)d_in[7],  (const float*)d_in[9],
                           (const float*)d_in[11], (const float*)d_in[13],
                           (const float*)d_in[15], (const float*)d_in[17] };
    const float* a2 = (const float*)d_in[18];
    const float* b2 = (const float*)d_in[19];
    float* out = (float*)d_out;

    __nv_bfloat16 *xhi, *xlo, *whi, *wlo, *phi, *plo, *ahi, *alo;
    float* scores;
    cudaGetSymbolAddress((void**)&xhi, g_xhi);
    cudaGetSymbolAddress((void**)&xlo, g_xlo);
    cudaGetSymbolAddress((void**)&whi, g_whi);
    cudaGetSymbolAddress((void**)&wlo, g_wlo);
    cudaGetSymbolAddress((void**)&phi, g_phi);
    cudaGetSymbolAddress((void**)&plo, g_plo);
    cudaGetSymbolAddress((void**)&ahi, g_ahi);
    cudaGetSymbolAddress((void**)&alo, g_alo);
    cudaGetSymbolAddress((void**)&scores, g_scores);

    // 1) split X and W into bf16 hi/lo planes
    for (int j = 0; j < 6; j++) {
        conv_split<<<(unsigned)(MS/4/256), 256>>>(
            (const float4*)X[j], (__nv_bfloat162*)(xhi + j*MS),
            (__nv_bfloat162*)(xlo + j*MS), MS/4);
        conv_split<<<(unsigned)(WS/4/256), 256>>>(
            (const float4*)W[j], (__nv_bfloat162*)(whi + j*WS),
            (__nv_bfloat162*)(wlo + j*WS), WS/4);
    }

    // 2) six projections: planes = split(X @ W^T + b); kr/vr/vi transposed
    // plane slots: 0 qr, 1 qi, 2 krT, 3 ki, 4 vrT, 5 viT
    {
        dim3 pg(8, 128, 1);
        for (int j = 0; j < 6; j++) {
            SegPtrs sp{};
            sp.a[0] = xhi + j*MS; sp.a[1] = xlo + j*MS; sp.a[2] = xhi + j*MS;
            sp.b[0] = whi + j*WS; sp.b[1] = whi + j*WS; sp.b[2] = wlo + j*WS;
            const bool tr = (j == 2 || j == 4 || j == 5);
            if (tr)
                tc_gemm<2><<<pg, 256>>>(sp, 3, 0, 0, nullptr, 0, 1.f,
                                        Bv[j], phi + j*MS, plo + j*MS);
            else
                tc_gemm<1><<<pg, 256>>>(sp, 3, 0, 0, nullptr, 0, 1.f,
                                        Bv[j], phi + j*MS, plo + j*MS);
        }
    }

    // 3) scores = (qr@krT^T + qi@ki^T) / 8  -> 6 segments, one GEMM
    {
        SegPtrs sp{};
        sp.a[0] = phi + 0*MS; sp.a[1] = plo + 0*MS; sp.a[2] = phi + 0*MS;
        sp.b[0] = phi + 2*MS; sp.b[1] = phi + 2*MS; sp.b[2] = plo + 2*MS;
        sp.a[3] = phi + 1*MS; sp.a[4] = plo + 1*MS; sp.a[5] = phi + 1*MS;
        sp.b[3] = phi + 3*MS; sp.b[4] = phi + 3*MS; sp.b[5] = plo + 3*MS;
        dim3 sg(8, 8, BATCH);
        tc_gemm<0><<<sg, 256>>>(sp, 6, SD, SD, scores, SD, 0.125f,
                                nullptr, nullptr, nullptr);
    }

    // 4) softmax -> attn hi/lo planes
    softmax_split<<<MTOT, 256>>>(scores, ahi, alo);

    // 5) out_r = attn @ vrT^T, out_i = attn @ viT^T (fp32 into d_out)
    {
        dim3 og(8, 8, BATCH);
        SegPtrs sr{};
        sr.a[0] = ahi; sr.a[1] = alo; sr.a[2] = ahi;
        sr.b[0] = phi + 4*MS; sr.b[1] = phi + 4*MS; sr.b[2] = plo + 4*MS;
        tc_gemm<0><<<og, 256>>>(sr, 3, SD, SD, out, SD, 1.f,
                                nullptr, nullptr, nullptr);
        SegPtrs si{};
        si.a[0] = ahi; si.a[1] = alo; si.a[2] = ahi;
        si.b[0] = phi + 5*MS; si.b[1] = phi + 5*MS; si.b[2] = plo + 5*MS;
        tc_gemm<0><<<og, 256>>>(si, 3, SD, SD, out + MS, SD, 1.f,
                                nullptr, nullptr, nullptr);
    }

    // 6) complex LayerNorm in place on d_out
    complex_ln_kernel<<<MTOT, 256>>>(out, a2, b2);
}

// round 9
// speedup vs baseline: 2.2717x; 1.0364x over previous
#include <cuda_runtime.h>
#include <cuda_bf16.h>
#include <math.h>
#include <stdint.h>

// Problem constants
#define BATCH 16
#define SEQ   1024
#define DIM   1024
#define MTOT  (BATCH*SEQ)            // 16384
#define MS    ((size_t)MTOT*DIM)     // 16777216
#define SD    ((size_t)SEQ*DIM)      // per-batch stride
#define WS    ((size_t)DIM*DIM)

// bf16 hi/lo planes (device globals; cudaMalloc forbidden)
__device__ __nv_bfloat16 g_xhi[6*MS], g_xlo[6*MS];
__device__ __nv_bfloat16 g_whi[6*WS], g_wlo[6*WS];
// proj planes, slots: 0 qr, 1 qi, 2 krT, 3 ki, 4 vrT, 5 viT
__device__ __nv_bfloat16 g_phi[6*MS], g_plo[6*MS];
// temp (untransposed) planes for kr, vr, vi
__device__ __nv_bfloat16 g_thi[3*MS], g_tlo[3*MS];
__device__ __nv_bfloat16 g_ahi[MS],  g_alo[MS];
__device__ float g_scores[(size_t)BATCH*SEQ*SEQ];

// ---------------------------------------------------------------------------
// helpers
// ---------------------------------------------------------------------------
__device__ __forceinline__ uint32_t smem_u32(const void* p) {
    uint32_t r;
    asm("{ .reg .u64 t; cvta.to.shared.u64 t, %1; cvt.u32.u64 %0, t; }"
        : "=r"(r) : "l"(p));
    return r;
}

__device__ __forceinline__ void cp16(uint32_t d, const void* s) {
    asm volatile("cp.async.cg.shared.global [%0], [%1], 16;" :: "r"(d), "l"(s));
}

__device__ __forceinline__ void ldmx4(uint32_t& r0, uint32_t& r1,
                                      uint32_t& r2, uint32_t& r3, uint32_t a) {
    asm volatile("ldmatrix.sync.aligned.m8n8.x4.shared.b16 {%0,%1,%2,%3}, [%4];"
                 : "=r"(r0), "=r"(r1), "=r"(r2), "=r"(r3) : "r"(a));
}

__device__ __forceinline__ void mma16816(float* c, const uint32_t* a,
                                         const uint32_t* b) {
    asm volatile(
        "mma.sync.aligned.m16n8k16.row.col.f32.bf16.bf16.f32 "
        "{%0,%1,%2,%3}, {%4,%5,%6,%7}, {%8,%9}, {%0,%1,%2,%3};"
        : "+f"(c[0]), "+f"(c[1]), "+f"(c[2]), "+f"(c[3])
        : "r"(a[0]), "r"(a[1]), "r"(a[2]), "r"(a[3]), "r"(b[0]), "r"(b[1]));
}

__device__ __forceinline__ void fsplit(float x, __nv_bfloat16& h, float& l) {
    h = __float2bfloat16(x);
    l = x - __bfloat162float(h);
}

// ---------------------------------------------------------------------------
// fp32 -> (hi, lo) bf16 planes, elementwise
// ---------------------------------------------------------------------------
__global__ __launch_bounds__(256)
void conv_split(const float4* __restrict__ in, __nv_bfloat162* __restrict__ hi,
                __nv_bfloat162* __restrict__ lo, size_t n4)
{
    size_t i = (size_t)blockIdx.x * 256 + threadIdx.x;
    if (i >= n4) return;
    float4 v = in[i];
    __nv_bfloat16 h0, h1, h2, h3; float l0, l1, l2, l3;
    fsplit(v.x, h0, l0); fsplit(v.y, h1, l1);
    fsplit(v.z, h2, l2); fsplit(v.w, h3, l3);
    hi[2*i]   = __halves2bfloat162(h0, h1);
    hi[2*i+1] = __halves2bfloat162(h2, h3);
    lo[2*i]   = __halves2bfloat162(__float2bfloat16(l0), __float2bfloat16(l1));
    lo[2*i+1] = __halves2bfloat162(__float2bfloat16(l2), __float2bfloat16(l3));
}

// ---------------------------------------------------------------------------
// Coalesced per-batch 1024x1024 bf16 transpose (64x64 smem tile, padded).
// ---------------------------------------------------------------------------
__global__ __launch_bounds__(256)
void transpose_bf16(const __nv_bfloat16* __restrict__ src,
                    __nv_bfloat16* __restrict__ dst)
{
    __shared__ __nv_bfloat16 t[64][66];
    const size_t bz = blockIdx.z;
    const __nv_bfloat16* s = src + bz * SD;
    __nv_bfloat16* d = dst + bz * SD;

    const int x = blockIdx.x * 64 + threadIdx.x * 2;
    const int y = blockIdx.y * 64 + threadIdx.y;
    #pragma unroll
    for (int j = 0; j < 64; j += 8) {
        __nv_bfloat162 v = *(const __nv_bfloat162*)(s + (size_t)(y + j) * 1024 + x);
        t[threadIdx.y + j][threadIdx.x * 2]     = v.x;
        t[threadIdx.y + j][threadIdx.x * 2 + 1] = v.y;
    }
    __syncthreads();
    const int xo = blockIdx.y * 64 + threadIdx.x * 2;
    const int yo = blockIdx.x * 64 + threadIdx.y;
    #pragma unroll
    for (int j = 0; j < 64; j += 8) {
        __nv_bfloat162 v = __halves2bfloat162(
            t[threadIdx.x * 2][threadIdx.y + j],
            t[threadIdx.x * 2 + 1][threadIdx.y + j]);
        *(__nv_bfloat162*)(d + (size_t)(yo + j) * 1024 + xo) = v;
    }
}

// ---------------------------------------------------------------------------
// Split-bf16 HMMA GEMM (3-stage cp.async ring, one sync per BK=32 iteration).
// C[m,n] = sum_seg Aseg[m,:] . Bseg[n,:]  (row-major, ld=1024, K=1024/seg)
// Tile 128x128, 8 warps (4x2), warp tile 32x64, mma m16n8k16.
// Epilogues: 0 = fp32*alpha, 1 = +bias -> split hi/lo bf16 planes.
// ---------------------------------------------------------------------------
#define RS 40                     // smem row stride in bf16 (80B)
#define OPBYTES (128*RS*2)        // 10240 per operand per stage
#define NSTAGE 3
#define GSMEM (NSTAGE*2*OPBYTES)  // 61440

struct SegPtrs { const __nv_bfloat16* a[6]; const __nv_bfloat16* b[6]; };

template<int EPI>
__global__ __launch_bounds__(256, 2)
void tc_gemm(SegPtrs segs, int nseg, size_t sA, size_t sB,
             float* __restrict__ Cf, size_t sC, float alpha,
             const float* __restrict__ bias,
             __nv_bfloat16* __restrict__ hiP, __nv_bfloat16* __restrict__ loP)
{
    extern __shared__ __align__(128) char sm[];
    __shared__ const __nv_bfloat16* sAp[6];
    __shared__ const __nv_bfloat16* sBp[6];

    const int tid = threadIdx.x;
    const int m0 = blockIdx.y * 128;
    const int n0 = blockIdx.x * 128;
    const size_t bz = blockIdx.z;

    if (tid < 6 && tid < nseg) {
        sAp[tid] = segs.a[tid] + bz * sA + (size_t)m0 * 1024;
        sBp[tid] = segs.b[tid] + bz * sB + (size_t)n0 * 1024;
    }
    __syncthreads();

    const uint32_t smb = smem_u32(sm);
    const int r0 = tid >> 2, c0 = tid & 3;
    const int NIT = nseg * 32;

    auto issue = [&](int it) {
        const int seg = it >> 5, kc = it & 31;
        const uint32_t st = smb + (uint32_t)(it % NSTAGE) * (2 * OPBYTES);
        const __nv_bfloat16* ga = sAp[seg] + kc * 32;
        const __nv_bfloat16* gb = sBp[seg] + kc * 32;
        cp16(st + r0 * 80 + c0 * 16,            ga + (size_t)r0 * 1024 + c0 * 8);
        cp16(st + (r0 + 64) * 80 + c0 * 16,     ga + (size_t)(r0 + 64) * 1024 + c0 * 8);
        cp16(st + OPBYTES + r0 * 80 + c0 * 16,        gb + (size_t)r0 * 1024 + c0 * 8);
        cp16(st + OPBYTES + (r0 + 64) * 80 + c0 * 16, gb + (size_t)(r0 + 64) * 1024 + c0 * 8);
    };

    float acc[2][8][4];
    #pragma unroll
    for (int i = 0; i < 2; i++)
        #pragma unroll
        for (int j = 0; j < 8; j++)
            #pragma unroll
            for (int k = 0; k < 4; k++) acc[i][j][k] = 0.f;

    const int lane = tid & 31, w = tid >> 5;
    const int wm = (w >> 1) * 32;
    const int wn = (w & 1) * 64;
    const uint32_t lmo = (uint32_t)((lane & 15) * 80 + (lane >> 4) * 16);

    issue(0);
    asm volatile("cp.async.commit_group;" ::: "memory");
    issue(1);
    asm volatile("cp.async.commit_group;" ::: "memory");

    for (int it = 0; it < NIT; ++it) {
        asm volatile("cp.async.wait_group 1;" ::: "memory");
        __syncthreads();
        if (it + 2 < NIT) issue(it + 2);
        asm volatile("cp.async.commit_group;" ::: "memory");

        const uint32_t stg = smb + (uint32_t)(it % NSTAGE) * (2 * OPBYTES);
        const uint32_t sa = stg + wm * 80 + lmo;
        const uint32_t sb = stg + OPBYTES + wn * 80 + lmo;

        #pragma unroll
        for (int ks = 0; ks < 2; ks++) {
            uint32_t A0[4], A1[4], Bf[8][2];
            ldmx4(A0[0], A0[1], A0[2], A0[3], sa + ks * 32);
            ldmx4(A1[0], A1[1], A1[2], A1[3], sa + 1280 + ks * 32);
            #pragma unroll
            for (int q = 0; q < 4; q++) {
                uint32_t t0, t1, t2, t3;
                ldmx4(t0, t1, t2, t3, sb + q * 1280 + ks * 32);
                Bf[2*q][0] = t0; Bf[2*q][1] = t2;
                Bf[2*q+1][0] = t1; Bf[2*q+1][1] = t3;
            }
            #pragma unroll
            for (int nt = 0; nt < 8; nt++) {
                mma16816(acc[0][nt], A0, Bf[nt]);
                mma16816(acc[1][nt], A1, Bf[nt]);
            }
        }
    }

    // Epilogue. Frag: g=lane>>2, t4=lane&3: c0,c1 -> (row g, cols 2t4,2t4+1),
    // c2,c3 -> (row g+8, same cols).
    const int g = lane >> 2, t4 = lane & 3;
    #pragma unroll
    for (int mt = 0; mt < 2; mt++) {
        #pragma unroll
        for (int nt = 0; nt < 8; nt++) {
            const int rowA = m0 + wm + mt * 16 + g;
            const int rowB = rowA + 8;
            const int col  = n0 + wn + nt * 8 + 2 * t4;
            float c0 = acc[mt][nt][0], c1 = acc[mt][nt][1];
            float c2 = acc[mt][nt][2], c3 = acc[mt][nt][3];
            if (EPI == 0) {
                float2 v0 = make_float2(c0 * alpha, c1 * alpha);
                float2 v1 = make_float2(c2 * alpha, c3 * alpha);
                *(float2*)(Cf + bz * sC + (size_t)rowA * 1024 + col) = v0;
                *(float2*)(Cf + bz * sC + (size_t)rowB * 1024 + col) = v1;
            } else {
                const float b0v = bias[col], b1v = bias[col + 1];
                const float v0 = c0 + b0v, v1 = c1 + b1v;
                const float v2 = c2 + b0v, v3 = c3 + b1v;
                __nv_bfloat16 h0, h1, h2, h3; float l0, l1, l2, l3;
                fsplit(v0, h0, l0); fsplit(v1, h1, l1);
                fsplit(v2, h2, l2); fsplit(v3, h3, l3);
                *(__nv_bfloat162*)(hiP + (size_t)rowA * 1024 + col) =
                    __halves2bfloat162(h0, h1);
                *(__nv_bfloat162*)(hiP + (size_t)rowB * 1024 + col) =
                    __halves2bfloat162(h2, h3);
                *(__nv_bfloat162*)(loP + (size_t)rowA * 1024 + col) =
                    __halves2bfloat162(__float2bfloat16(l0), __float2bfloat16(l1));
                *(__nv_bfloat162*)(loP + (size_t)rowB * 1024 + col) =
                    __halves2bfloat162(__float2bfloat16(l2), __float2bfloat16(l3));
            }
        }
    }
}

// ---------------------------------------------------------------------------
// Row softmax over 1024, writes attn hi/lo bf16 planes.
// ---------------------------------------------------------------------------
__global__ __launch_bounds__(256)
void softmax_split(const float* __restrict__ s, __nv_bfloat16* __restrict__ hi,
                   __nv_bfloat16* __restrict__ lo)
{
    const size_t row = blockIdx.x;
    const float4* p = (const float4*)(s + row * 1024);
    const int tid = threadIdx.x;

    float4 v = p[tid];
    float m = fmaxf(fmaxf(v.x, v.y), fmaxf(v.z, v.w));
    #pragma unroll
    for (int o = 16; o > 0; o >>= 1)
        m = fmaxf(m, __shfl_xor_sync(0xffffffffu, m, o));

    __shared__ float red[8];
    __shared__ float fin[2];
    if ((tid & 31) == 0) red[tid >> 5] = m;
    __syncthreads();
    if (tid < 32) {
        float t = (tid < 8) ? red[tid] : -3.4e38f;
        #pragma unroll
        for (int o = 4; o > 0; o >>= 1)
            t = fmaxf(t, __shfl_xor_sync(0xffffffffu, t, o));
        if (tid == 0) fin[0] = t;
    }
    __syncthreads();
    m = fin[0];

    v.x = expf(v.x - m); v.y = expf(v.y - m);
    v.z = expf(v.z - m); v.w = expf(v.w - m);
    float sum = v.x + v.y + v.z + v.w;
    #pragma unroll
    for (int o = 16; o > 0; o >>= 1)
        sum += __shfl_xor_sync(0xffffffffu, sum, o);
    if ((tid & 31) == 0) red[tid >> 5] = sum;
    __syncthreads();
    if (tid < 32) {
        float t = (tid < 8) ? red[tid] : 0.f;
        #pragma unroll
        for (int o = 4; o > 0; o >>= 1)
            t += __shfl_xor_sync(0xffffffffu, t, o);
        if (tid == 0) fin[1] = t;
    }
    __syncthreads();
    const float inv = 1.0f / fin[1];
    v.x *= inv; v.y *= inv; v.z *= inv; v.w *= inv;

    __nv_bfloat16 h0, h1, h2, h3; float l0, l1, l2, l3;
    fsplit(v.x, h0, l0); fsplit(v.y, h1, l1);
    fsplit(v.z, h2, l2); fsplit(v.w, h3, l3);
    __nv_bfloat162* ph = (__nv_bfloat162*)(hi + row * 1024 + tid * 4);
    __nv_bfloat162* pl = (__nv_bfloat162*)(lo + row * 1024 + tid * 4);
    ph[0] = __halves2bfloat162(h0, h1);
    ph[1] = __halves2bfloat162(h2, h3);
    pl[0] = __halves2bfloat162(__float2bfloat16(l0), __float2bfloat16(l1));
    pl[1] = __halves2bfloat162(__float2bfloat16(l2), __float2bfloat16(l3));
}

// ---------------------------------------------------------------------------
// Complex LayerNorm, in place on out = [2, B*S, D].
// ---------------------------------------------------------------------------
__global__ __launch_bounds__(256)
void complex_ln_kernel(float* __restrict__ out,
                       const float* __restrict__ a2,
                       const float* __restrict__ b2)
{
    const size_t row = blockIdx.x;
    float* pr = out + row * 1024;
    float* pi = out + MS + row * 1024;
    const int tid = threadIdx.x;

    float4 zr = ((float4*)pr)[tid];
    float4 zi = ((float4*)pi)[tid];

    float sv[5];
    sv[0] = zr.x + zr.y + zr.z + zr.w;
    sv[1] = zi.x + zi.y + zi.z + zi.w;
    sv[2] = zr.x*zr.x + zr.y*zr.y + zr.z*zr.z + zr.w*zr.w;
    sv[3] = zi.x*zi.x + zi.y*zi.y + zi.z*zi.z + zi.w*zi.w;
    sv[4] = zr.x*zi.x + zr.y*zi.y + zr.z*zi.z + zr.w*zi.w;

    #pragma unroll
    for (int u = 0; u < 5; u++)
        #pragma unroll
        for (int o = 16; o > 0; o >>= 1)
            sv[u] += __shfl_xor_sync(0xffffffffu, sv[u], o);

    __shared__ float red[5][8];
    __shared__ float fin[5];
    if ((tid & 31) == 0) {
        #pragma unroll
        for (int u = 0; u < 5; u++) red[u][tid >> 5] = sv[u];
    }
    __syncthreads();
    if (tid == 0) {
        #pragma unroll
        for (int u = 0; u < 5; u++) {
            float t = 0.f;
            #pragma unroll
            for (int wv = 0; wv < 8; wv++) t += red[u][wv];
            fin[u] = t;
        }
    }
    __syncthreads();

    const float invD = 1.0f / 1024.0f;
    const float mr = fin[0] * invD;
    const float mi = fin[1] * invD;
    const float err = fin[2] * invD - mr * mr;
    const float eii = fin[3] * invD - mi * mi;
    const float eri = fin[4] * invD - mr * mi;
    const float vr = err - eii + 1e-6f;
    const float vi = 2.0f * eri;
    const float rmod = sqrtf(vr * vr + vi * vi);
    const float sre = sqrtf(fmaxf(0.5f * (rmod + vr), 0.f));
    const float sim = copysignf(sqrtf(fmaxf(0.5f * (rmod - vr), 0.f)), vi);
    const float inv = 1.0f / fmaxf(rmod, 1e-30f);

    float4 ga = ((const float4*)a2)[tid];
    float4 gb = ((const float4*)b2)[tid];

    float4 yr, yi;
    {
        float ar = zr.x - mr, ai = zi.x - mi;
        yr.x = (ar * sre + ai * sim) * inv; yi.x = (ai * sre - ar * sim) * inv;
        ar = zr.y - mr; ai = zi.y - mi;
        yr.y = (ar * sre + ai * sim) * inv; yi.y = (ai * sre - ar * sim) * inv;
        ar = zr.z - mr; ai = zi.z - mi;
        yr.z = (ar * sre + ai * sim) * inv; yi.z = (ai * sre - ar * sim) * inv;
        ar = zr.w - mr; ai = zi.w - mi;
        yr.w = (ar * sre + ai * sim) * inv; yi.w = (ai * sre - ar * sim) * inv;
    }
    yr.x = ga.x * yr.x + gb.x; yi.x = ga.x * yi.x;
    yr.y = ga.y * yr.y + gb.y; yi.y = ga.y * yi.y;
    yr.z = ga.z * yr.z + gb.z; yi.z = ga.z * yi.z;
    yr.w = ga.w * yr.w + gb.w; yi.w = ga.w * yi.w;

    ((float4*)pr)[tid] = yr;
    ((float4*)pi)[tid] = yi;
}

// ---------------------------------------------------------------------------
extern "C" void kernel_launch(void* const* d_in, const int* in_sizes, int n_in,
                              void* d_out, int out_size)
{
    const float* X[6]  = { (const float*)d_in[0], (const float*)d_in[1],
                           (const float*)d_in[2], (const float*)d_in[3],
                           (const float*)d_in[4], (const float*)d_in[5] };
    const float* W[6]  = { (const float*)d_in[6],  (const float*)d_in[8],
                           (const float*)d_in[10], (const float*)d_in[12],
                           (const float*)d_in[14], (const float*)d_in[16] };
    const float* Bv[6] = { (const float*)d_in[7],  (const float*)d_in[9],
                           (const float*)d_in[11], (const float*)d_in[13],
                           (const float*)d_in[15], (const float*)d_in[17] };
    const float* a2 = (const float*)d_in[18];
    const float* b2 = (const float*)d_in[19];
    float* out = (float*)d_out;

    __nv_bfloat16 *xhi, *xlo, *whi, *wlo, *phi, *plo, *thi, *tlo, *ahi, *alo;
    float* scores;
    cudaGetSymbolAddress((void**)&xhi, g_xhi);
    cudaGetSymbolAddress((void**)&xlo, g_xlo);
    cudaGetSymbolAddress((void**)&whi, g_whi);
    cudaGetSymbolAddress((void**)&wlo, g_wlo);
    cudaGetSymbolAddress((void**)&phi, g_phi);
    cudaGetSymbolAddress((void**)&plo, g_plo);
    cudaGetSymbolAddress((void**)&thi, g_thi);
    cudaGetSymbolAddress((void**)&tlo, g_tlo);
    cudaGetSymbolAddress((void**)&ahi, g_ahi);
    cudaGetSymbolAddress((void**)&alo, g_alo);
    cudaGetSymbolAddress((void**)&scores, g_scores);

    cudaFuncSetAttribute(tc_gemm<0>,
        cudaFuncAttributeMaxDynamicSharedMemorySize, GSMEM);
    cudaFuncSetAttribute(tc_gemm<1>,
        cudaFuncAttributeMaxDynamicSharedMemorySize, GSMEM);

    // 1) split X and W into bf16 hi/lo planes
    for (int j = 0; j < 6; j++) {
        conv_split<<<(unsigned)(MS/4/256), 256>>>(
            (const float4*)X[j], (__nv_bfloat162*)(xhi + j*MS),
            (__nv_bfloat162*)(xlo + j*MS), MS/4);
        conv_split<<<(unsigned)(WS/4/256), 256>>>(
            (const float4*)W[j], (__nv_bfloat162*)(whi + j*WS),
            (__nv_bfloat162*)(wlo + j*WS), WS/4);
    }

    // 2) six projections (all plain plane writes). kr/vr/vi -> temp slots.
    // final slots: 0 qr, 1 qi, 2 krT, 3 ki, 4 vrT, 5 viT
    {
        dim3 pg(8, 128, 1);
        // temp slot index for j in {2,4,5}: 0,1,2
        for (int j = 0; j < 6; j++) {
            SegPtrs sp{};
            sp.a[0] = xhi + j*MS; sp.a[1] = xlo + j*MS; sp.a[2] = xhi + j*MS;
            sp.b[0] = whi + j*WS; sp.b[1] = whi + j*WS; sp.b[2] = wlo + j*WS;
            __nv_bfloat16 *dh, *dl;
            if (j == 2)      { dh = thi + 0*MS; dl = tlo + 0*MS; }
            else if (j == 4) { dh = thi + 1*MS; dl = tlo + 1*MS; }
            else if (j == 5) { dh = thi + 2*MS; dl = tlo + 2*MS; }
            else             { dh = phi + j*MS; dl = plo + j*MS; }
            tc_gemm<1><<<pg, 256, GSMEM>>>(sp, 3, 0, 0, nullptr, 0, 1.f,
                                           Bv[j], dh, dl);
        }
    }

    // 2b) coalesced bf16 transposes: temp -> slots 2 (krT), 4 (vrT), 5 (viT)
    {
        dim3 tg(16, 16, BATCH);
        dim3 tb(32, 8);
        transpose_bf16<<<tg, tb>>>(thi + 0*MS, phi + 2*MS);
        transpose_bf16<<<tg, tb>>>(tlo + 0*MS, plo + 2*MS);
        transpose_bf16<<<tg, tb>>>(thi + 1*MS, phi + 4*MS);
        transpose_bf16<<<tg, tb>>>(tlo + 1*MS, plo + 4*MS);
        transpose_bf16<<<tg, tb>>>(thi + 2*MS, phi + 5*MS);
        transpose_bf16<<<tg, tb>>>(tlo + 2*MS, plo + 5*MS);
    }

    // 3) scores = (qr@krT^T + qi@ki^T) / 8  -> 6 segments, one GEMM
    {
        SegPtrs sp{};
        sp.a[0] = phi + 0*MS; sp.a[1] = plo + 0*MS; sp.a[2] = phi + 0*MS;
        sp.b[0] = phi + 2*MS; sp.b[1] = phi + 2*MS; sp.b[2] = plo + 2*MS;
        sp.a[3] = phi + 1*MS; sp.a[4] = plo + 1*MS; sp.a[5] = phi + 1*MS;
        sp.b[3] = phi + 3*MS; sp.b[4] = phi + 3*MS; sp.b[5] = plo + 3*MS;
        dim3 sg(8, 8, BATCH);
        tc_gemm<0><<<sg, 256, GSMEM>>>(sp, 6, SD, SD, scores, SD, 0.125f,
                                       nullptr, nullptr, nullptr);
    }

    // 4) softmax -> attn hi/lo planes
    softmax_split<<<MTOT, 256>>>(scores, ahi, alo);

    // 5) out_r = attn @ vrT^T, out_i = attn @ viT^T (fp32 into d_out)
    {
        dim3 og(8, 8, BATCH);
        SegPtrs sr{};
        sr.a[0] = ahi; sr.a[1] = alo; sr.a[2] = ahi;
        sr.b[0] = phi + 4*MS; sr.b[1] = phi + 4*MS; sr.b[2] = plo + 4*MS;
        tc_gemm<0><<<og, 256, GSMEM>>>(sr, 3, SD, SD, out, SD, 1.f,
                                       nullptr, nullptr, nullptr);
        SegPtrs si{};
        si.a[0] = ahi; si.a[1] = alo; si.a[2] = ahi;
        si.b[0] = phi + 5*MS; si.b[1] = phi + 5*MS; si.b[2] = plo + 5*MS;
        tc_gemm<0><<<og, 256, GSMEM>>>(si, 3, SD, SD, out + MS, SD, 1.f,
                                       nullptr, nullptr, nullptr);
    }

    // 6) complex LayerNorm in place on d_out
    complex_ln_kernel<<<MTOT, 256>>>(out, a2, b2);
}